// round 9
// baseline (speedup 1.0000x reference)
#include <cuda_runtime.h>
#include <cuda_bf16.h>
#include <cuda_fp16.h>
#include <cstdint>

#define NMAX 100000
#define EMAX 1600000
#define SCAN_BLK 1024

// ---------------------------------------------------------------------------
// Device scratch (allocation-free rule)
// ---------------------------------------------------------------------------
__device__ int    g_deg [NMAX];
__device__ int    g_off [NMAX];
__device__ int    g_cur [NMAX];
__device__ int    g_part[256];
__device__ int    g_csr [EMAX];
__device__ float  g_dinv[NMAX];
__device__ __align__(16) __half g_h1 [(size_t)NMAX * 128];
__device__ __align__(16) __half g_a1 [(size_t)NMAX * 128];
__device__ __align__(16) __half g_h2 [(size_t)NMAX * 64];
__device__ __align__(16) uint32_t g_w1hi[8192], g_w1lo[8192];
__device__ __align__(16) uint32_t g_w2hi[4096], g_w2lo[4096];

// ---------------------------------------------------------------------------
// Helpers
// ---------------------------------------------------------------------------
__device__ __forceinline__ void mma_bf16(float* c, const uint32_t* a, const uint32_t* b) {
    asm volatile("mma.sync.aligned.m16n8k16.row.col.f32.bf16.bf16.f32 "
                 "{%0,%1,%2,%3}, {%4,%5,%6,%7}, {%8,%9}, {%0,%1,%2,%3};"
                 : "+f"(c[0]), "+f"(c[1]), "+f"(c[2]), "+f"(c[3])
                 : "r"(a[0]), "r"(a[1]), "r"(a[2]), "r"(a[3]), "r"(b[0]), "r"(b[1]));
}
__device__ __forceinline__ uint32_t pack_bf16(float a, float b) {
    __nv_bfloat162 h = __floats2bfloat162_rn(a, b);
    return *(uint32_t*)&h;
}
__device__ __forceinline__ uint32_t f2_to_h2(float x, float y) {
    __half2 h = __floats2half2_rn(x, y);
    return *(uint32_t*)&h;
}
__device__ __forceinline__ float4 h4_to_f4(uint2 v) {
    float2 fa = __half22float2(*(__half2*)&v.x);
    float2 fb = __half22float2(*(__half2*)&v.y);
    return make_float4(fa.x, fa.y, fb.x, fb.y);
}

// ---------------------------------------------------------------------------
// CSR build (degree histogram + scan + fill)
// ---------------------------------------------------------------------------
__global__ void k_deg(const int* __restrict__ ei, int E) {
    int i = blockIdx.x * blockDim.x + threadIdx.x;
    if (i < E) atomicAdd(&g_deg[ei[E + i]], 1);
}
__global__ void k_scan1(int n) {
    __shared__ int sw[32];
    int tid = threadIdx.x;
    int i = blockIdx.x * SCAN_BLK + tid;
    int v = (i < n) ? g_deg[i] : 0;
    int x = v;
    #pragma unroll
    for (int o = 1; o < 32; o <<= 1) {
        int y = __shfl_up_sync(0xffffffffu, x, o);
        if ((tid & 31) >= o) x += y;
    }
    if ((tid & 31) == 31) sw[tid >> 5] = x;
    __syncthreads();
    if (tid < 32) {
        int y = sw[tid];
        #pragma unroll
        for (int o = 1; o < 32; o <<= 1) {
            int z = __shfl_up_sync(0xffffffffu, y, o);
            if (tid >= o) y += z;
        }
        sw[tid] = y;
    }
    __syncthreads();
    int wp = (tid >= 32) ? sw[(tid >> 5) - 1] : 0;
    if (i < n) g_off[i] = wp + x - v;
    if (tid == SCAN_BLK - 1) g_part[blockIdx.x] = wp + x;
}
__global__ void k_scan2(int nb) {
    __shared__ int sw[4];
    int t = threadIdx.x;
    int v = (t < nb) ? g_part[t] : 0;
    int x = v;
    #pragma unroll
    for (int o = 1; o < 32; o <<= 1) {
        int y = __shfl_up_sync(0xffffffffu, x, o);
        if ((t & 31) >= o) x += y;
    }
    if ((t & 31) == 31) sw[t >> 5] = x;
    __syncthreads();
    if (t == 0) {
        int run = 0;
        #pragma unroll
        for (int j = 0; j < 4; j++) { int tmp = sw[j]; sw[j] = run; run += tmp; }
    }
    __syncthreads();
    int wp = sw[t >> 5];
    if (t < nb) g_part[t] = wp + x - v;
}
__global__ void k_finish(int n) {
    int i = blockIdx.x * blockDim.x + threadIdx.x;
    if (i >= n) return;
    int off = g_off[i] + g_part[i >> 10];
    g_off[i] = off;
    g_cur[i] = off;
    g_dinv[i] = rsqrtf((float)(g_deg[i] + 1));
}
__global__ void k_fill(const int* __restrict__ ei, int E) {
    int e = blockIdx.x * blockDim.x + threadIdx.x;
    if (e >= E) return;
    int s = ei[e];
    int d = ei[E + e];
    int p = atomicAdd(&g_cur[d], 1);
    g_csr[p] = s;
}

// ---------------------------------------------------------------------------
// Weight prep (both weights in one launch; globals bound in device code)
// grid: blocks 0..31 -> W1 (8192 pairs), blocks 32..47 -> W2 (4096 pairs)
// ---------------------------------------------------------------------------
__global__ void k_wprep_all(const float* __restrict__ W1, const float* __restrict__ W2) {
    int gi = blockIdx.x * blockDim.x + threadIdx.x;
    const float* W;
    uint32_t *bhi, *blo;
    int i, Nc;
    if (gi < 8192) {
        W = W1; bhi = g_w1hi; blo = g_w1lo; i = gi; Nc = 128;
    } else {
        gi -= 8192;
        if (gi >= 4096) return;
        W = W2; bhi = g_w2hi; blo = g_w2lo; i = gi; Nc = 64;
    }
    int nn = i >> 6;
    int k2 = i & 63;
    int k = k2 << 1;
    float v0 = W[k * Nc + nn];
    float v1 = W[(k + 1) * Nc + nn];
    __nv_bfloat16 h0 = __float2bfloat16(v0);
    __nv_bfloat16 h1 = __float2bfloat16(v1);
    uint32_t hi = (uint32_t)(*(uint16_t*)&h0) | ((uint32_t)(*(uint16_t*)&h1) << 16);
    uint32_t lo = pack_bf16(v0 - __bfloat162float(h0), v1 - __bfloat162float(h1));
    bhi[nn * 64 + k2] = hi;
    blo[nn * 64 + k2] = lo;
}

// ---------------------------------------------------------------------------
// Tensor-core GEMM via mma.sync bf16x3: Od(fp16) = dinv[row] * (A @ W)
// MODE 1: A = x (fp32 ext) -> g_h1 (no dinv yet: dinv computed on branch;
//         join happens before gather so scale moved there? NO — keep dinv here;
//         GEMM1 runs concurrently with CSR branch, so dinv may not be ready.
//         FIX: MODE 1 stores unscaled h1; gather1 applies dinv[s] per source.
// MODE 2: A = g_a1 (fp16) -> g_h2 (dinv ready by then; scale in epilogue).
// ---------------------------------------------------------------------------
template <int NCOL, int MODE>
__launch_bounds__(256, 1)
__global__ void k_tc_gemm(const float* __restrict__ Aext, int n) {
    constexpr int TR  = 64;
    constexpr int NWM = (NCOL == 128) ? 2 : 4;
    constexpr int MF  = TR / (NWM * 16);
    constexpr int NWN = 8 / NWM;
    constexpr int NF  = NCOL / (NWN * 8);
    constexpr int STR = 272;
    constexpr int A_HI = 0;
    constexpr int A_LO = TR * STR;
    constexpr int B_HI = 2 * TR * STR;
    constexpr int B_LO = B_HI + NCOL * STR;

    extern __shared__ char smraw[];
    char* sm = smraw;

    const int tid  = threadIdx.x;
    const int wid  = tid >> 5;
    const int lane = tid & 31;
    const int row0 = blockIdx.x * TR;

    __half* Od = (MODE == 1) ? g_h1 : g_h2;
    const uint32_t* Bhig = (MODE == 1) ? g_w1hi : g_w2hi;
    const uint32_t* Blog = (MODE == 1) ? g_w1lo : g_w2lo;

    {
        const uint4* bh4 = (const uint4*)Bhig;
        const uint4* bl4 = (const uint4*)Blog;
        constexpr int NB4 = NCOL * 16;
        #pragma unroll
        for (int i = tid; i < NB4; i += 256) {
            int r  = i >> 4;
            int kc = i & 15;
            *(uint4*)(sm + B_HI + r * STR + kc * 16) = bh4[i];
            *(uint4*)(sm + B_LO + r * STR + kc * 16) = bl4[i];
        }
    }

    #pragma unroll
    for (int i = tid; i < TR * 16; i += 256) {
        int r  = i >> 4;
        int kc = i & 15;
        int gr = row0 + r;
        float f[8];
        if (MODE == 1) {
            float4 va = make_float4(0.f, 0.f, 0.f, 0.f);
            float4 vb = make_float4(0.f, 0.f, 0.f, 0.f);
            if (gr < n) {
                va = ((const float4*)Aext)[(size_t)gr * 32 + kc * 2];
                vb = ((const float4*)Aext)[(size_t)gr * 32 + kc * 2 + 1];
            }
            f[0] = va.x; f[1] = va.y; f[2] = va.z; f[3] = va.w;
            f[4] = vb.x; f[5] = vb.y; f[6] = vb.z; f[7] = vb.w;
        } else {
            uint4 v = make_uint4(0u, 0u, 0u, 0u);
            if (gr < n) v = ((const uint4*)g_a1)[(size_t)gr * 16 + kc];
            float2 f0 = __half22float2(*(__half2*)&v.x);
            float2 f1 = __half22float2(*(__half2*)&v.y);
            float2 f2 = __half22float2(*(__half2*)&v.z);
            float2 f3 = __half22float2(*(__half2*)&v.w);
            f[0] = f0.x; f[1] = f0.y; f[2] = f1.x; f[3] = f1.y;
            f[4] = f2.x; f[5] = f2.y; f[6] = f3.x; f[7] = f3.y;
        }
        uint4 hi, lo;
        uint32_t* hp = (uint32_t*)&hi;
        uint32_t* lp = (uint32_t*)&lo;
        #pragma unroll
        for (int j = 0; j < 4; j++) {
            __nv_bfloat162 h = __floats2bfloat162_rn(f[2 * j], f[2 * j + 1]);
            hp[j] = *(uint32_t*)&h;
            lp[j] = pack_bf16(f[2 * j]     - __bfloat162float(h.x),
                              f[2 * j + 1] - __bfloat162float(h.y));
        }
        *(uint4*)(sm + A_HI + r * STR + kc * 16) = hi;
        *(uint4*)(sm + A_LO + r * STR + kc * 16) = lo;
    }
    __syncthreads();

    const int wm   = wid % NWM;
    const int wn   = wid / NWM;
    const int mrow = wm * (MF * 16);
    const int ncol = wn * (NF * 8);
    const int gr4  = lane >> 2;
    const int cl2  = (lane & 3) * 2;

    float acc[MF][NF][4];
    #pragma unroll
    for (int mf = 0; mf < MF; mf++)
        #pragma unroll
        for (int nf = 0; nf < NF; nf++)
            #pragma unroll
            for (int j = 0; j < 4; j++) acc[mf][nf][j] = 0.f;

    #pragma unroll
    for (int ks = 0; ks < 8; ks++) {
        const int kb = (ks * 16 + cl2) * 2;
        uint32_t ahi[MF][4], alo[MF][4];
        #pragma unroll
        for (int mf = 0; mf < MF; mf++) {
            int ro = (mrow + mf * 16 + gr4) * STR + kb;
            ahi[mf][0] = *(const uint32_t*)(sm + A_HI + ro);
            ahi[mf][1] = *(const uint32_t*)(sm + A_HI + ro + 8 * STR);
            ahi[mf][2] = *(const uint32_t*)(sm + A_HI + ro + 16);
            ahi[mf][3] = *(const uint32_t*)(sm + A_HI + ro + 8 * STR + 16);
            alo[mf][0] = *(const uint32_t*)(sm + A_LO + ro);
            alo[mf][1] = *(const uint32_t*)(sm + A_LO + ro + 8 * STR);
            alo[mf][2] = *(const uint32_t*)(sm + A_LO + ro + 16);
            alo[mf][3] = *(const uint32_t*)(sm + A_LO + ro + 8 * STR + 16);
        }
        uint32_t bhi[NF][2], blo[NF][2];
        #pragma unroll
        for (int nf = 0; nf < NF; nf++) {
            int ro = (ncol + nf * 8 + gr4) * STR + kb;
            bhi[nf][0] = *(const uint32_t*)(sm + B_HI + ro);
            bhi[nf][1] = *(const uint32_t*)(sm + B_HI + ro + 16);
            blo[nf][0] = *(const uint32_t*)(sm + B_LO + ro);
            blo[nf][1] = *(const uint32_t*)(sm + B_LO + ro + 16);
        }
        #pragma unroll
        for (int mf = 0; mf < MF; mf++)
            #pragma unroll
            for (int nf = 0; nf < NF; nf++) {
                mma_bf16(acc[mf][nf], ahi[mf], bhi[nf]);
                mma_bf16(acc[mf][nf], ahi[mf], blo[nf]);
                mma_bf16(acc[mf][nf], alo[mf], bhi[nf]);
            }
    }

    // Epilogue. MODE 1: store UNSCALED (dinv not ready; applied in gather1).
    //           MODE 2: scale by dinv[row] here.
    #pragma unroll
    for (int mf = 0; mf < MF; mf++) {
        int r0g = row0 + mrow + mf * 16 + gr4;
        int r1g = r0g + 8;
        float dv0 = 1.f, dv1 = 1.f;
        if (MODE == 2) {
            dv0 = (r0g < n) ? g_dinv[r0g] : 0.f;
            dv1 = (r1g < n) ? g_dinv[r1g] : 0.f;
        }
        #pragma unroll
        for (int nf = 0; nf < NF; nf++) {
            int c = ncol + nf * 8 + cl2;
            if (r0g < n) {
                uint32_t p = f2_to_h2(acc[mf][nf][0] * dv0, acc[mf][nf][1] * dv0);
                *(uint32_t*)&Od[(size_t)r0g * NCOL + c] = p;
            }
            if (r1g < n) {
                uint32_t p = f2_to_h2(acc[mf][nf][2] * dv1, acc[mf][nf][3] * dv1);
                *(uint32_t*)&Od[(size_t)r1g * NCOL + c] = p;
            }
        }
    }
}

// ---------------------------------------------------------------------------
// Gather aggregation. gather1 now applies dinv[s] per neighbor (h1 unscaled):
// g_a1[d] = fp16(relu(dinv[d]*(dinv[d]*h1[d] + sum dinv[s]*h1[s]) + b1))
// ---------------------------------------------------------------------------
__global__ void k_gather1(const float* __restrict__ b1, int n) {
    int t = blockIdx.x * blockDim.x + threadIdx.x;
    int lane = t & 31;
    int w = t >> 5;
    if (w >= n) return;
    int st = g_off[w], cnt = g_deg[w];
    const uint2* H = (const uint2*)g_h1;
    float dvw = g_dinv[w];
    float4 self = h4_to_f4(H[(size_t)w * 32 + lane]);
    float4 acc = make_float4(self.x * dvw, self.y * dvw, self.z * dvw, self.w * dvw);
    int j = 0;
    for (; j + 4 <= cnt; j += 4) {
        int s0 = g_csr[st + j], s1 = g_csr[st + j + 1];
        int s2 = g_csr[st + j + 2], s3 = g_csr[st + j + 3];
        float d0 = g_dinv[s0], d1 = g_dinv[s1], d2 = g_dinv[s2], d3 = g_dinv[s3];
        float4 v0 = h4_to_f4(H[(size_t)s0 * 32 + lane]);
        float4 v1 = h4_to_f4(H[(size_t)s1 * 32 + lane]);
        float4 v2 = h4_to_f4(H[(size_t)s2 * 32 + lane]);
        float4 v3 = h4_to_f4(H[(size_t)s3 * 32 + lane]);
        acc.x += (v0.x * d0 + v1.x * d1) + (v2.x * d2 + v3.x * d3);
        acc.y += (v0.y * d0 + v1.y * d1) + (v2.y * d2 + v3.y * d3);
        acc.z += (v0.z * d0 + v1.z * d1) + (v2.z * d2 + v3.z * d3);
        acc.w += (v0.w * d0 + v1.w * d1) + (v2.w * d2 + v3.w * d3);
    }
    for (; j < cnt; j++) {
        int s = g_csr[st + j];
        float ds = g_dinv[s];
        float4 v = h4_to_f4(H[(size_t)s * 32 + lane]);
        acc.x += v.x * ds; acc.y += v.y * ds; acc.z += v.z * ds; acc.w += v.w * ds;
    }
    float4 b = ((const float4*)b1)[lane];
    float ox = fmaxf(fmaf(acc.x, dvw, b.x), 0.f);
    float oy = fmaxf(fmaf(acc.y, dvw, b.y), 0.f);
    float oz = fmaxf(fmaf(acc.z, dvw, b.z), 0.f);
    float ow = fmaxf(fmaf(acc.w, dvw, b.w), 0.f);
    uint2 o;
    o.x = f2_to_h2(ox, oy);
    o.y = f2_to_h2(oz, ow);
    ((uint2*)g_a1)[(size_t)w * 32 + lane] = o;
}

__global__ void k_gather2(float* __restrict__ out, const float* __restrict__ b2, int n) {
    int t = blockIdx.x * blockDim.x + threadIdx.x;
    int ch = t & 15;
    int g = t >> 4;
    if (g >= n) return;
    int st = g_off[g], cnt = g_deg[g];
    const uint2* H = (const uint2*)g_h2;
    float4 acc = h4_to_f4(H[(size_t)g * 16 + ch]);
    int j = 0;
    for (; j + 4 <= cnt; j += 4) {
        int s0 = g_csr[st + j], s1 = g_csr[st + j + 1];
        int s2 = g_csr[st + j + 2], s3 = g_csr[st + j + 3];
        float4 v0 = h4_to_f4(H[(size_t)s0 * 16 + ch]);
        float4 v1 = h4_to_f4(H[(size_t)s1 * 16 + ch]);
        float4 v2 = h4_to_f4(H[(size_t)s2 * 16 + ch]);
        float4 v3 = h4_to_f4(H[(size_t)s3 * 16 + ch]);
        acc.x += (v0.x + v1.x) + (v2.x + v3.x);
        acc.y += (v0.y + v1.y) + (v2.y + v3.y);
        acc.z += (v0.z + v1.z) + (v2.z + v3.z);
        acc.w += (v0.w + v1.w) + (v2.w + v3.w);
    }
    for (; j < cnt; j++) {
        int s = g_csr[st + j];
        float4 v = h4_to_f4(H[(size_t)s * 16 + ch]);
        acc.x += v.x; acc.y += v.y; acc.z += v.z; acc.w += v.w;
    }
    float dv = g_dinv[g];
    float4 b = ((const float4*)b2)[ch];
    acc.x = fmaf(acc.x, dv, b.x);
    acc.y = fmaf(acc.y, dv, b.y);
    acc.z = fmaf(acc.z, dv, b.z);
    acc.w = fmaf(acc.w, dv, b.w);
    ((float4*)out)[(size_t)g * 16 + ch] = acc;
}

// ---------------------------------------------------------------------------
// Launch: fork/join graph — CSR branch runs concurrently with wprep+GEMM1
// ---------------------------------------------------------------------------
extern "C" void kernel_launch(void* const* d_in, const int* in_sizes, int n_in,
                              void* d_out, int out_size) {
    const float* x  = (const float*)d_in[0];
    const int*   ei = (const int*)  d_in[1];
    const float* W1 = (const float*)d_in[2];
    const float* b1 = (const float*)d_in[3];
    const float* W2 = (const float*)d_in[4];
    const float* b2 = (const float*)d_in[5];
    float* out = (float*)d_out;

    const int n = in_sizes[0] / 128;
    const int E = in_sizes[1] / 2;
    const int nb = (n + SCAN_BLK - 1) / SCAN_BLK;

    const int smem1 = 2 * 64 * 272 + 2 * 128 * 272;  // 104448
    const int smem2 = 2 * 64 * 272 + 2 * 64  * 272;  //  69632
    cudaFuncSetAttribute(k_tc_gemm<128, 1>, cudaFuncAttributeMaxDynamicSharedMemorySize, smem1);
    cudaFuncSetAttribute(k_tc_gemm<64,  2>, cudaFuncAttributeMaxDynamicSharedMemorySize, smem2);

    // Side stream + events for the independent CSR branch (created per call;
    // intentionally not destroyed — destroying a forked stream mid-capture
    // invalidates the capture; leak is a few handles over ~5 calls).
    cudaStream_t s2;
    cudaStreamCreateWithFlags(&s2, cudaStreamNonBlocking);
    cudaEvent_t evFork, evJoin;
    cudaEventCreateWithFlags(&evFork, cudaEventDisableTiming);
    cudaEventCreateWithFlags(&evJoin, cudaEventDisableTiming);

    // Fork
    cudaEventRecord(evFork, 0);
    cudaStreamWaitEvent(s2, evFork, 0);

    // Branch A (s2): CSR build + dinv
    int* degp = nullptr;
    cudaGetSymbolAddress((void**)&degp, g_deg);
    cudaMemsetAsync(degp, 0, n * sizeof(int), s2);
    k_deg<<<(E + 255) / 256, 256, 0, s2>>>(ei, E);
    k_scan1<<<nb, SCAN_BLK, 0, s2>>>(n);
    k_scan2<<<1, 128, 0, s2>>>(nb);
    k_finish<<<(n + 255) / 256, 256, 0, s2>>>(n);
    k_fill<<<(E + 255) / 256, 256, 0, s2>>>(ei, E);
    cudaEventRecord(evJoin, s2);

    // Branch B (main stream): weight prep + conv1 GEMM (h1 unscaled)
    const int gg = (n + 63) / 64;
    k_wprep_all<<<48, 256>>>(W1, W2);
    k_tc_gemm<128, 1><<<gg, 256, smem1>>>(x, n);

    // Join: gather1 needs CSR + dinv + h1
    cudaStreamWaitEvent(0, evJoin, 0);
    k_gather1<<<(n * 32 + 255) / 256, 256>>>(b1, n);

    // conv2
    k_tc_gemm<64, 2><<<gg, 256, smem2>>>(nullptr, n);
    k_gather2<<<(n * 16 + 255) / 256, 256>>>(out, b2, n);
}

// round 10
// speedup vs baseline: 1.0490x; 1.0490x over previous
#include <cuda_runtime.h>
#include <cuda_bf16.h>
#include <cuda_fp16.h>
#include <cstdint>

#define NMAX 100000
#define EMAX 1600000
#define SCAN_BLK 1024

// ---------------------------------------------------------------------------
// Device scratch (allocation-free rule)
// ---------------------------------------------------------------------------
__device__ int    g_deg [NMAX];
__device__ int    g_off [NMAX];
__device__ int    g_cur [NMAX];
__device__ int    g_part[256];
__device__ int    g_csr [EMAX];
__device__ float  g_dinv[NMAX];
__device__ __align__(16) __half g_h1 [(size_t)NMAX * 128];
__device__ __align__(16) __half g_a1 [(size_t)NMAX * 128];
__device__ __align__(16) __half g_h2 [(size_t)NMAX * 64];
__device__ __align__(16) uint32_t g_w1hi[8192], g_w1lo[8192];
__device__ __align__(16) uint32_t g_w2hi[4096], g_w2lo[4096];

// ---------------------------------------------------------------------------
// Helpers
// ---------------------------------------------------------------------------
__device__ __forceinline__ uint32_t smem_u32(const void* p) {
    uint32_t a;
    asm("{ .reg .u64 t; cvta.to.shared.u64 t, %1; cvt.u32.u64 %0, t; }" : "=r"(a) : "l"(p));
    return a;
}
__device__ __forceinline__ void ldsm_x4(uint32_t addr, uint32_t& r0, uint32_t& r1,
                                        uint32_t& r2, uint32_t& r3) {
    asm volatile("ldmatrix.sync.aligned.m8n8.x4.shared.b16 {%0,%1,%2,%3}, [%4];"
                 : "=r"(r0), "=r"(r1), "=r"(r2), "=r"(r3) : "r"(addr));
}
__device__ __forceinline__ void mma_bf16(float* c, const uint32_t* a, const uint32_t* b) {
    asm volatile("mma.sync.aligned.m16n8k16.row.col.f32.bf16.bf16.f32 "
                 "{%0,%1,%2,%3}, {%4,%5,%6,%7}, {%8,%9}, {%0,%1,%2,%3};"
                 : "+f"(c[0]), "+f"(c[1]), "+f"(c[2]), "+f"(c[3])
                 : "r"(a[0]), "r"(a[1]), "r"(a[2]), "r"(a[3]), "r"(b[0]), "r"(b[1]));
}
__device__ __forceinline__ uint32_t pack_bf16(float a, float b) {
    __nv_bfloat162 h = __floats2bfloat162_rn(a, b);
    return *(uint32_t*)&h;
}
__device__ __forceinline__ uint32_t f2_to_h2(float x, float y) {
    __half2 h = __floats2half2_rn(x, y);
    return *(uint32_t*)&h;
}
__device__ __forceinline__ float4 h4_to_f4(uint2 v) {
    float2 fa = __half22float2(*(__half2*)&v.x);
    float2 fb = __half22float2(*(__half2*)&v.y);
    return make_float4(fa.x, fa.y, fb.x, fb.y);
}

// ---------------------------------------------------------------------------
// CSR build (degree histogram + scan + fill)
// ---------------------------------------------------------------------------
__global__ void k_deg(const int* __restrict__ ei, int E) {
    int i = blockIdx.x * blockDim.x + threadIdx.x;
    if (i < E) atomicAdd(&g_deg[ei[E + i]], 1);
}
__global__ void k_scan1(int n) {
    __shared__ int sw[32];
    int tid = threadIdx.x;
    int i = blockIdx.x * SCAN_BLK + tid;
    int v = (i < n) ? g_deg[i] : 0;
    int x = v;
    #pragma unroll
    for (int o = 1; o < 32; o <<= 1) {
        int y = __shfl_up_sync(0xffffffffu, x, o);
        if ((tid & 31) >= o) x += y;
    }
    if ((tid & 31) == 31) sw[tid >> 5] = x;
    __syncthreads();
    if (tid < 32) {
        int y = sw[tid];
        #pragma unroll
        for (int o = 1; o < 32; o <<= 1) {
            int z = __shfl_up_sync(0xffffffffu, y, o);
            if (tid >= o) y += z;
        }
        sw[tid] = y;
    }
    __syncthreads();
    int wp = (tid >= 32) ? sw[(tid >> 5) - 1] : 0;
    if (i < n) g_off[i] = wp + x - v;
    if (tid == SCAN_BLK - 1) g_part[blockIdx.x] = wp + x;
}
__global__ void k_scan2(int nb) {
    __shared__ int sw[4];
    int t = threadIdx.x;
    int v = (t < nb) ? g_part[t] : 0;
    int x = v;
    #pragma unroll
    for (int o = 1; o < 32; o <<= 1) {
        int y = __shfl_up_sync(0xffffffffu, x, o);
        if ((t & 31) >= o) x += y;
    }
    if ((t & 31) == 31) sw[t >> 5] = x;
    __syncthreads();
    if (t == 0) {
        int run = 0;
        #pragma unroll
        for (int j = 0; j < 4; j++) { int tmp = sw[j]; sw[j] = run; run += tmp; }
    }
    __syncthreads();
    int wp = sw[t >> 5];
    if (t < nb) g_part[t] = wp + x - v;
}
__global__ void k_finish(int n) {
    int i = blockIdx.x * blockDim.x + threadIdx.x;
    if (i >= n) return;
    int off = g_off[i] + g_part[i >> 10];
    g_off[i] = off;
    g_cur[i] = off;
    g_dinv[i] = rsqrtf((float)(g_deg[i] + 1));
}
__global__ void k_fill(const int* __restrict__ ei, int E) {
    int e = blockIdx.x * blockDim.x + threadIdx.x;
    if (e >= E) return;
    int s = ei[e];
    int d = ei[E + e];
    int p = atomicAdd(&g_cur[d], 1);
    g_csr[p] = s;
}

// ---------------------------------------------------------------------------
// Weight prep (fused, globals bound in device code)
// ---------------------------------------------------------------------------
__global__ void k_wprep_all(const float* __restrict__ W1, const float* __restrict__ W2) {
    int gi = blockIdx.x * blockDim.x + threadIdx.x;
    const float* W;
    uint32_t *bhi, *blo;
    int i, Nc;
    if (gi < 8192) {
        W = W1; bhi = g_w1hi; blo = g_w1lo; i = gi; Nc = 128;
    } else {
        gi -= 8192;
        if (gi >= 4096) return;
        W = W2; bhi = g_w2hi; blo = g_w2lo; i = gi; Nc = 64;
    }
    int nn = i >> 6;
    int k2 = i & 63;
    int k = k2 << 1;
    float v0 = W[k * Nc + nn];
    float v1 = W[(k + 1) * Nc + nn];
    __nv_bfloat16 h0 = __float2bfloat16(v0);
    __nv_bfloat16 h1 = __float2bfloat16(v1);
    uint32_t hi = (uint32_t)(*(uint16_t*)&h0) | ((uint32_t)(*(uint16_t*)&h1) << 16);
    uint32_t lo = pack_bf16(v0 - __bfloat162float(h0), v1 - __bfloat162float(h1));
    bhi[nn * 64 + k2] = hi;
    blo[nn * 64 + k2] = lo;
}

// ---------------------------------------------------------------------------
// Tensor-core GEMM via mma.sync bf16x3 + ldmatrix fragment loads.
// Od(fp16) = dinv[row] * (A @ W).  Padded SMEM rows (STR=272B) are
// conflict-free for ldmatrix: word offset of row r = 4r mod 32, so an
// 8-row x 16B matrix read covers all 32 banks exactly once.
// MODE 1: A = x (fp32 ext) -> g_h1.  MODE 2: A = g_a1 (fp16) -> g_h2.
// ---------------------------------------------------------------------------
template <int NCOL, int MODE>
__launch_bounds__(256, 1)
__global__ void k_tc_gemm(const float* __restrict__ Aext, int n) {
    constexpr int TR  = 64;
    constexpr int NWM = (NCOL == 128) ? 2 : 4;
    constexpr int MF  = TR / (NWM * 16);
    constexpr int NWN = 8 / NWM;
    constexpr int NF  = NCOL / (NWN * 8);
    constexpr int STR = 272;
    constexpr int A_HI = 0;
    constexpr int A_LO = TR * STR;
    constexpr int B_HI = 2 * TR * STR;
    constexpr int B_LO = B_HI + NCOL * STR;

    extern __shared__ char smraw[];
    char* sm = smraw;
    const uint32_t smb = smem_u32(smraw);

    const int tid  = threadIdx.x;
    const int wid  = tid >> 5;
    const int lane = tid & 31;
    const int row0 = blockIdx.x * TR;

    __half* Od = (MODE == 1) ? g_h1 : g_h2;
    const uint32_t* Bhig = (MODE == 1) ? g_w1hi : g_w2hi;
    const uint32_t* Blog = (MODE == 1) ? g_w1lo : g_w2lo;

    // Stage weights: dense 256B rows -> padded 272B rows
    {
        const uint4* bh4 = (const uint4*)Bhig;
        const uint4* bl4 = (const uint4*)Blog;
        constexpr int NB4 = NCOL * 16;
        #pragma unroll
        for (int i = tid; i < NB4; i += 256) {
            int r  = i >> 4;
            int kc = i & 15;
            *(uint4*)(sm + B_HI + r * STR + kc * 16) = bh4[i];
            *(uint4*)(sm + B_LO + r * STR + kc * 16) = bl4[i];
        }
    }

    // Load + split-convert A tile (64 x 128 -> bf16 hi/lo)
    #pragma unroll
    for (int i = tid; i < TR * 16; i += 256) {
        int r  = i >> 4;
        int kc = i & 15;
        int gr = row0 + r;
        float f[8];
        if (MODE == 1) {
            float4 va = make_float4(0.f, 0.f, 0.f, 0.f);
            float4 vb = make_float4(0.f, 0.f, 0.f, 0.f);
            if (gr < n) {
                va = ((const float4*)Aext)[(size_t)gr * 32 + kc * 2];
                vb = ((const float4*)Aext)[(size_t)gr * 32 + kc * 2 + 1];
            }
            f[0] = va.x; f[1] = va.y; f[2] = va.z; f[3] = va.w;
            f[4] = vb.x; f[5] = vb.y; f[6] = vb.z; f[7] = vb.w;
        } else {
            uint4 v = make_uint4(0u, 0u, 0u, 0u);
            if (gr < n) v = ((const uint4*)g_a1)[(size_t)gr * 16 + kc];
            float2 f0 = __half22float2(*(__half2*)&v.x);
            float2 f1 = __half22float2(*(__half2*)&v.y);
            float2 f2 = __half22float2(*(__half2*)&v.z);
            float2 f3 = __half22float2(*(__half2*)&v.w);
            f[0] = f0.x; f[1] = f0.y; f[2] = f1.x; f[3] = f1.y;
            f[4] = f2.x; f[5] = f2.y; f[6] = f3.x; f[7] = f3.y;
        }
        uint4 hi, lo;
        uint32_t* hp = (uint32_t*)&hi;
        uint32_t* lp = (uint32_t*)&lo;
        #pragma unroll
        for (int j = 0; j < 4; j++) {
            __nv_bfloat162 h = __floats2bfloat162_rn(f[2 * j], f[2 * j + 1]);
            hp[j] = *(uint32_t*)&h;
            lp[j] = pack_bf16(f[2 * j]     - __bfloat162float(h.x),
                              f[2 * j + 1] - __bfloat162float(h.y));
        }
        *(uint4*)(sm + A_HI + r * STR + kc * 16) = hi;
        *(uint4*)(sm + A_LO + r * STR + kc * 16) = lo;
    }
    __syncthreads();

    const int wm   = wid % NWM;
    const int wn   = wid / NWM;
    const int mrow = wm * (MF * 16);
    const int ncol = wn * (NF * 8);
    const int lrow = lane & 7;
    const int sel  = lane >> 3;
    const int gr4  = lane >> 2;
    const int cl2  = (lane & 3) * 2;

    // Per-lane ldmatrix address components
    const int arow = mrow + lrow + ((sel & 1) << 3);   // + mf*16
    const int akb  = (sel >> 1) << 4;                  // + ks*32
    const int brow = ncol + lrow + ((sel >> 1) << 3);  // + nf*8 (pairs)
    const int bkb  = (sel & 1) << 4;                   // + ks*32

    float acc[MF][NF][4];
    #pragma unroll
    for (int mf = 0; mf < MF; mf++)
        #pragma unroll
        for (int nf = 0; nf < NF; nf++)
            #pragma unroll
            for (int j = 0; j < 4; j++) acc[mf][nf][j] = 0.f;

    #pragma unroll
    for (int ks = 0; ks < 8; ks++) {
        uint32_t ahi[MF][4], alo[MF][4];
        #pragma unroll
        for (int mf = 0; mf < MF; mf++) {
            uint32_t off = (uint32_t)((arow + mf * 16) * STR + ks * 32 + akb);
            ldsm_x4(smb + A_HI + off, ahi[mf][0], ahi[mf][1], ahi[mf][2], ahi[mf][3]);
            ldsm_x4(smb + A_LO + off, alo[mf][0], alo[mf][1], alo[mf][2], alo[mf][3]);
        }
        uint32_t bhi[NF][2], blo[NF][2];
        #pragma unroll
        for (int nf = 0; nf < NF; nf += 2) {
            uint32_t off = (uint32_t)((brow + nf * 8) * STR + ks * 32 + bkb);
            ldsm_x4(smb + B_HI + off, bhi[nf][0], bhi[nf][1], bhi[nf + 1][0], bhi[nf + 1][1]);
            ldsm_x4(smb + B_LO + off, blo[nf][0], blo[nf][1], blo[nf + 1][0], blo[nf + 1][1]);
        }
        #pragma unroll
        for (int mf = 0; mf < MF; mf++)
            #pragma unroll
            for (int nf = 0; nf < NF; nf++) {
                mma_bf16(acc[mf][nf], ahi[mf], bhi[nf]);
                mma_bf16(acc[mf][nf], ahi[mf], blo[nf]);
                mma_bf16(acc[mf][nf], alo[mf], bhi[nf]);
            }
    }

    // Epilogue: scale by dinv[row], store half2 per fragment half
    #pragma unroll
    for (int mf = 0; mf < MF; mf++) {
        int r0g = row0 + mrow + mf * 16 + gr4;
        int r1g = r0g + 8;
        float dv0 = (r0g < n) ? g_dinv[r0g] : 0.f;
        float dv1 = (r1g < n) ? g_dinv[r1g] : 0.f;
        #pragma unroll
        for (int nf = 0; nf < NF; nf++) {
            int c = ncol + nf * 8 + cl2;
            if (r0g < n) {
                uint32_t p = f2_to_h2(acc[mf][nf][0] * dv0, acc[mf][nf][1] * dv0);
                *(uint32_t*)&Od[(size_t)r0g * NCOL + c] = p;
            }
            if (r1g < n) {
                uint32_t p = f2_to_h2(acc[mf][nf][2] * dv1, acc[mf][nf][3] * dv1);
                *(uint32_t*)&Od[(size_t)r1g * NCOL + c] = p;
            }
        }
    }
}

// ---------------------------------------------------------------------------
// Gather aggregation (CSR, no atomics), fp16 reads, fp32 accumulate (R8 form)
// ---------------------------------------------------------------------------
__global__ void k_gather1(const float* __restrict__ b1, int n) {
    int t = blockIdx.x * blockDim.x + threadIdx.x;
    int lane = t & 31;
    int w = t >> 5;
    if (w >= n) return;
    int st = g_off[w], cnt = g_deg[w];
    const uint2* H = (const uint2*)g_h1;
    float4 acc = h4_to_f4(H[(size_t)w * 32 + lane]);
    int j = 0;
    for (; j + 4 <= cnt; j += 4) {
        int s0 = g_csr[st + j], s1 = g_csr[st + j + 1];
        int s2 = g_csr[st + j + 2], s3 = g_csr[st + j + 3];
        float4 v0 = h4_to_f4(H[(size_t)s0 * 32 + lane]);
        float4 v1 = h4_to_f4(H[(size_t)s1 * 32 + lane]);
        float4 v2 = h4_to_f4(H[(size_t)s2 * 32 + lane]);
        float4 v3 = h4_to_f4(H[(size_t)s3 * 32 + lane]);
        acc.x += (v0.x + v1.x) + (v2.x + v3.x);
        acc.y += (v0.y + v1.y) + (v2.y + v3.y);
        acc.z += (v0.z + v1.z) + (v2.z + v3.z);
        acc.w += (v0.w + v1.w) + (v2.w + v3.w);
    }
    for (; j < cnt; j++) {
        int s = g_csr[st + j];
        float4 v = h4_to_f4(H[(size_t)s * 32 + lane]);
        acc.x += v.x; acc.y += v.y; acc.z += v.z; acc.w += v.w;
    }
    float dv = g_dinv[w];
    float4 b = ((const float4*)b1)[lane];
    float ox = fmaxf(fmaf(acc.x, dv, b.x), 0.f);
    float oy = fmaxf(fmaf(acc.y, dv, b.y), 0.f);
    float oz = fmaxf(fmaf(acc.z, dv, b.z), 0.f);
    float ow = fmaxf(fmaf(acc.w, dv, b.w), 0.f);
    uint2 o;
    o.x = f2_to_h2(ox, oy);
    o.y = f2_to_h2(oz, ow);
    ((uint2*)g_a1)[(size_t)w * 32 + lane] = o;
}

__global__ void k_gather2(float* __restrict__ out, const float* __restrict__ b2, int n) {
    int t = blockIdx.x * blockDim.x + threadIdx.x;
    int ch = t & 15;
    int g = t >> 4;
    if (g >= n) return;
    int st = g_off[g], cnt = g_deg[g];
    const uint2* H = (const uint2*)g_h2;
    float4 acc = h4_to_f4(H[(size_t)g * 16 + ch]);
    int j = 0;
    for (; j + 4 <= cnt; j += 4) {
        int s0 = g_csr[st + j], s1 = g_csr[st + j + 1];
        int s2 = g_csr[st + j + 2], s3 = g_csr[st + j + 3];
        float4 v0 = h4_to_f4(H[(size_t)s0 * 16 + ch]);
        float4 v1 = h4_to_f4(H[(size_t)s1 * 16 + ch]);
        float4 v2 = h4_to_f4(H[(size_t)s2 * 16 + ch]);
        float4 v3 = h4_to_f4(H[(size_t)s3 * 16 + ch]);
        acc.x += (v0.x + v1.x) + (v2.x + v3.x);
        acc.y += (v0.y + v1.y) + (v2.y + v3.y);
        acc.z += (v0.z + v1.z) + (v2.z + v3.z);
        acc.w += (v0.w + v1.w) + (v2.w + v3.w);
    }
    for (; j < cnt; j++) {
        int s = g_csr[st + j];
        float4 v = h4_to_f4(H[(size_t)s * 16 + ch]);
        acc.x += v.x; acc.y += v.y; acc.z += v.z; acc.w += v.w;
    }
    float dv = g_dinv[g];
    float4 b = ((const float4*)b2)[ch];
    acc.x = fmaf(acc.x, dv, b.x);
    acc.y = fmaf(acc.y, dv, b.y);
    acc.z = fmaf(acc.z, dv, b.z);
    acc.w = fmaf(acc.w, dv, b.w);
    ((float4*)out)[(size_t)g * 16 + ch] = acc;
}

// ---------------------------------------------------------------------------
// Launch (sequential — R9 overlap regressed; reverted)
// ---------------------------------------------------------------------------
extern "C" void kernel_launch(void* const* d_in, const int* in_sizes, int n_in,
                              void* d_out, int out_size) {
    const float* x  = (const float*)d_in[0];
    const int*   ei = (const int*)  d_in[1];
    const float* W1 = (const float*)d_in[2];
    const float* b1 = (const float*)d_in[3];
    const float* W2 = (const float*)d_in[4];
    const float* b2 = (const float*)d_in[5];
    float* out = (float*)d_out;

    const int n = in_sizes[0] / 128;
    const int E = in_sizes[1] / 2;
    const int nb = (n + SCAN_BLK - 1) / SCAN_BLK;

    const int smem1 = 2 * 64 * 272 + 2 * 128 * 272;  // 104448
    const int smem2 = 2 * 64 * 272 + 2 * 64  * 272;  //  69632
    cudaFuncSetAttribute(k_tc_gemm<128, 1>, cudaFuncAttributeMaxDynamicSharedMemorySize, smem1);
    cudaFuncSetAttribute(k_tc_gemm<64,  2>, cudaFuncAttributeMaxDynamicSharedMemorySize, smem2);

    // Weight prep (one launch)
    k_wprep_all<<<48, 256>>>(W1, W2);

    // CSR build + normalization
    int* degp = nullptr;
    cudaGetSymbolAddress((void**)&degp, g_deg);
    cudaMemsetAsync(degp, 0, n * sizeof(int), 0);
    k_deg<<<(E + 255) / 256, 256>>>(ei, E);
    k_scan1<<<nb, SCAN_BLK>>>(n);
    k_scan2<<<1, 128>>>(nb);
    k_finish<<<(n + 255) / 256, 256>>>(n);
    k_fill<<<(E + 255) / 256, 256>>>(ei, E);

    const int gg = (n + 63) / 64;

    // conv1
    k_tc_gemm<128, 1><<<gg, 256, smem1>>>(x, n);
    k_gather1<<<(n * 32 + 255) / 256, 256>>>(b1, n);

    // conv2
    k_tc_gemm<64, 2><<<gg, 256, smem2>>>(nullptr, n);
    k_gather2<<<(n * 16 + 255) / 256, 256>>>(out, b2, n);
}